// round 4
// baseline (speedup 1.0000x reference)
#include <cuda_runtime.h>
#include <cstdint>
#include <cstddef>

typedef unsigned long long ull;

#define BATCH   32
#define T_STEPS 2048
#define HID     256
#define BT      (BATCH * T_STEPS)         // 65536
#define GCOLS   768                       // [r(256) | z(256) | n(256)] input-side gates

// Scratch for input-side projections: (BT, 768) fp32 = 192 MB (static, no cudaMalloc)
__device__ float g_xproj[(size_t)BT * GCOLS];

// ---------------------------------------------------------------------------
// helpers
// ---------------------------------------------------------------------------
__device__ __forceinline__ void ffma2(ull& d, ull a, ull b) {
    // packed dual-fp32 FMA (Blackwell): d.lo += a.lo*b.lo ; d.hi += a.hi*b.hi
    asm("fma.rn.f32x2 %0, %1, %2, %0;" : "+l"(d) : "l"(a), "l"(b));
}

__device__ __forceinline__ float tanh_fast(float x) {
    float y;
    asm("tanh.approx.f32 %0, %1;" : "=f"(y) : "f"(x));
    return y;
}

__device__ __forceinline__ float sigmoid_fast(float x) {
    // sigmoid(x) = 0.5*tanh(0.5x) + 0.5
    return fmaf(0.5f, tanh_fast(0.5f * x), 0.5f);
}

__device__ __forceinline__ void st_cluster_f32(uint32_t addr, uint32_t rank, float v) {
    uint32_t ra;
    asm volatile("mapa.shared::cluster.u32 %0, %1, %2;" : "=r"(ra) : "r"(addr), "r"(rank));
    asm volatile("st.shared::cluster.f32 [%0], %1;" :: "r"(ra), "f"(v) : "memory");
}

// ---------------------------------------------------------------------------
// Kernel 1: input projection GEMM
//   g_xproj[m, n] = sum_k x[m,k] * Wcat[n,k] + bcat[n]
//   Wcat rows: n<512 -> W_irz[n], n>=512 -> W_in[n-512]
// Tile: M=64 x N=128 x K=256 (full K in smem). 128 threads, 8x8 reg tile,
// k-pairs packed into f32x2 accumulators.
// ---------------------------------------------------------------------------
#define PROJ_SMEM_BYTES ((64*256 + 128*260) * 4)   // As 64KB + Bs (pitch 260) 130KB

__global__ void __launch_bounds__(128, 1) proj_kernel(
    const float* __restrict__ x,
    const float* __restrict__ W_irz, const float* __restrict__ b_irz,
    const float* __restrict__ W_in,  const float* __restrict__ b_in)
{
    extern __shared__ float smem[];
    float* As = smem;               // [64][256]
    float* Bs = smem + 64 * 256;    // [128] rows, pitch 260 floats

    const int tid = threadIdx.x;
    const int m0 = blockIdx.x * 64;
    const int n0 = blockIdx.y * 128;

    const float* Wsrc; const float* bsrc;
    if (n0 < 512) { Wsrc = W_irz + (size_t)n0 * 256;         bsrc = b_irz + n0; }
    else          { Wsrc = W_in  + (size_t)(n0 - 512) * 256; bsrc = b_in + (n0 - 512); }

    {
        const float4* xg = (const float4*)(x + (size_t)m0 * 256);
        float4* As4 = (float4*)As;
        #pragma unroll
        for (int it = 0; it < 32; it++) {
            int idx = it * 128 + tid;
            As4[idx] = xg[idx];
        }
        const float4* wg = (const float4*)Wsrc;
        #pragma unroll
        for (int it = 0; it < 64; it++) {
            int idx = it * 128 + tid;
            int n = idx >> 6, k4 = idx & 63;
            *(float4*)(Bs + n * 260 + (k4 << 2)) = wg[idx];
        }
    }
    __syncthreads();

    const int lane = tid & 31, warp = tid >> 5;
    const int cg = lane & 15;
    const int rg2 = lane >> 4;
    const int rglob = warp * 2 + rg2;

    ull acc[64];
    #pragma unroll
    for (int i = 0; i < 64; i++) acc[i] = 0ull;

    const ull* Au = (const ull*)As;
    const ull* Bu = (const ull*)Bs;

    int aoff[8], boff[8];
    #pragma unroll
    for (int i = 0; i < 8; i++) aoff[i] = (rglob + 8 * i) * 128;
    #pragma unroll
    for (int j = 0; j < 8; j++) boff[j] = (cg + 16 * j) * 130;

    #pragma unroll 2
    for (int kk = 0; kk < 128; kk++) {
        ull a2[8], b2[8];
        #pragma unroll
        for (int i = 0; i < 8; i++) a2[i] = Au[aoff[i] + kk];
        #pragma unroll
        for (int j = 0; j < 8; j++) b2[j] = Bu[boff[j] + kk];
        #pragma unroll
        for (int i = 0; i < 8; i++)
            #pragma unroll
            for (int j = 0; j < 8; j++)
                ffma2(acc[i * 8 + j], a2[i], b2[j]);
    }

    float bias[8];
    #pragma unroll
    for (int j = 0; j < 8; j++) bias[j] = bsrc[cg + 16 * j];

    #pragma unroll
    for (int i = 0; i < 8; i++) {
        int m = rglob + 8 * i;
        float* orow = g_xproj + (size_t)(m0 + m) * GCOLS + n0;
        #pragma unroll
        for (int j = 0; j < 8; j++) {
            union { ull u; float f[2]; } v; v.u = acc[i * 8 + j];
            orow[cg + 16 * j] = v.f[0] + v.f[1] + bias[j];
        }
    }
}

// ---------------------------------------------------------------------------
// Kernel 2: persistent GRU recurrence.
// Cluster of 4 CTAs per batch element (grid 128). 256 threads per CTA.
// Thread (u, q): u = tid>>2 (hidden unit within CTA's 64), q = tid&3 (k-quarter).
// Each thread holds the r/z/n weight rows of its unit over k in [64q, 64q+64)
// in registers (96 ull = 192 floats). One h-quarter load feeds all 3 rows.
// Reduction: 2 butterfly shfl rounds over the 4 quarter lanes; all 4 lanes
// compute the epilogue redundantly (no divergence, no smem, no syncthreads);
// lane q ships h_new to cluster CTA rank q (parallel DSMEM fan-out).
// One barrier.cluster per step (double-buffered h).
// ---------------------------------------------------------------------------
__global__ void __cluster_dims__(4, 1, 1) __launch_bounds__(256, 1)
gru_kernel(const float* __restrict__ h0,
           const float* __restrict__ W_hrz, const float* __restrict__ b_hrz,
           const float* __restrict__ W_hn,  const float* __restrict__ b_hn,
           float* __restrict__ out, int write_hn)
{
    __shared__ __align__(16) float hbuf[2][HID];

    const int tid  = threadIdx.x;
    const int b    = blockIdx.x >> 2;
    const int rank = blockIdx.x & 3;
    const int u    = tid >> 2;        // unit within CTA: 0..63
    const int q    = tid & 3;         // k-quarter: 0..3
    const int j    = rank * 64 + u;   // global hidden unit 0..255

    // ---- register-resident weights: 3 rows x 64 floats over this quarter ----
    ull wr[32], wz[32], wn[32];
    {
        const ull* pr = (const ull*)(W_hrz + (size_t)j * 256)         + q * 32;
        const ull* pz = (const ull*)(W_hrz + (size_t)(256 + j) * 256) + q * 32;
        const ull* pn = (const ull*)(W_hn  + (size_t)j * 256)         + q * 32;
        #pragma unroll
        for (int i = 0; i < 32; i++) { wr[i] = pr[i]; wz[i] = pz[i]; wn[i] = pn[i]; }
    }
    const float bhr = b_hrz[j];
    const float bhz = b_hrz[256 + j];
    const float bhn = b_hn[j];

    hbuf[0][tid] = h0[(size_t)b * HID + tid];
    __syncthreads();
    asm volatile("barrier.cluster.arrive.aligned;" ::: "memory");
    asm volatile("barrier.cluster.wait.aligned;"  ::: "memory");

    const float* xbase = g_xproj + (size_t)b * T_STEPS * GCOLS;
    float* obase = out + (size_t)b * T_STEPS * HID;

    const uint32_t sa_base0 = (uint32_t)__cvta_generic_to_shared(&hbuf[0][j]);
    const uint32_t sa_base1 = (uint32_t)__cvta_generic_to_shared(&hbuf[1][j]);

    // x-side gate inputs for t=0
    float xr = xbase[j], xz = xbase[256 + j], xn = xbase[512 + j];

    float hnew = 0.0f;

    for (int t = 0; t < T_STEPS; t++) {
        const int par = t & 1;

        // branchless prefetch of next step's x (clamped index, DRAM latency
        // hidden under this step's FMA + barrier)
        const int tn = (t + 1 < T_STEPS) ? (t + 1) : (T_STEPS - 1);
        const float* xp = xbase + (size_t)tn * GCOLS;
        const float nxr = xp[j], nxz = xp[256 + j], nxn = xp[512 + j];

        // ---- matvec: this thread's k-quarter of its unit's r/z/n rows ----
        ull ar = 0ull, az = 0ull, an = 0ull;
        const float4* h4 = (const float4*)hbuf[par] + q * 16;
        #pragma unroll
        for (int i = 0; i < 16; i++) {
            union { float4 f; ull u[2]; } hv;
            hv.f = h4[i];
            ffma2(ar, wr[2 * i],     hv.u[0]);
            ffma2(ar, wr[2 * i + 1], hv.u[1]);
            ffma2(az, wz[2 * i],     hv.u[0]);
            ffma2(az, wz[2 * i + 1], hv.u[1]);
            ffma2(an, wn[2 * i],     hv.u[0]);
            ffma2(an, wn[2 * i + 1], hv.u[1]);
        }
        union { ull u; float f[2]; } vr, vz, vn;
        vr.u = ar; vz.u = az; vn.u = an;
        float sr = vr.f[0] + vr.f[1];
        float sz = vz.f[0] + vz.f[1];
        float sn = vn.f[0] + vn.f[1];
        // butterfly reduce across the 4 quarter-lanes (all lanes get full sums)
        sr += __shfl_xor_sync(0xffffffffu, sr, 1);
        sz += __shfl_xor_sync(0xffffffffu, sz, 1);
        sn += __shfl_xor_sync(0xffffffffu, sn, 1);
        sr += __shfl_xor_sync(0xffffffffu, sr, 2);
        sz += __shfl_xor_sync(0xffffffffu, sz, 2);
        sn += __shfl_xor_sync(0xffffffffu, sn, 2);

        // ---- epilogue (all 4 lanes redundantly; zero divergence) ----
        float r = sigmoid_fast(sr + bhr + xr);
        float z = sigmoid_fast(sz + bhz + xz);
        float n = tanh_fast(fmaf(r, sn + bhn, xn));
        float hold = hbuf[par][j];
        hnew = fmaf(z, hold - n, n);              // (1-z)*n + z*h

        if (q == 0) obase[(size_t)t * HID + j] = hnew;

        // lane q delivers h_new to cluster CTA rank q (parallel fan-out)
        uint32_t sa = (par ? sa_base0 : sa_base1);  // write into buffer par^1
        st_cluster_f32(sa, (uint32_t)q, hnew);

        xr = nxr; xz = nxz; xn = nxn;

        asm volatile("barrier.cluster.arrive.aligned;" ::: "memory");
        asm volatile("barrier.cluster.wait.aligned;"  ::: "memory");
    }

    if (write_hn && q == 0)
        out[(size_t)BATCH * T_STEPS * HID + (size_t)b * HID + j] = hnew;
}

// ---------------------------------------------------------------------------
// launch
// ---------------------------------------------------------------------------
extern "C" void kernel_launch(void* const* d_in, const int* in_sizes, int n_in,
                              void* d_out, int out_size)
{
    (void)in_sizes; (void)n_in;
    const float* x     = (const float*)d_in[0];
    const float* h0    = (const float*)d_in[1];
    const float* W_irz = (const float*)d_in[2];
    const float* b_irz = (const float*)d_in[3];
    const float* W_hrz = (const float*)d_in[4];
    const float* b_hrz = (const float*)d_in[5];
    const float* W_in  = (const float*)d_in[6];
    const float* b_in  = (const float*)d_in[7];
    const float* W_hn  = (const float*)d_in[8];
    const float* b_hn  = (const float*)d_in[9];
    float* out = (float*)d_out;

    cudaFuncSetAttribute(proj_kernel, cudaFuncAttributeMaxDynamicSharedMemorySize,
                         PROJ_SMEM_BYTES);
    cudaFuncSetAttribute(gru_kernel, cudaFuncAttributeNonPortableClusterSizeAllowed, 1);

    proj_kernel<<<dim3(BT / 64, GCOLS / 128, 1), 128, PROJ_SMEM_BYTES>>>(
        x, W_irz, b_irz, W_in, b_in);

    const long long need_hn = (long long)BATCH * T_STEPS * HID + (long long)BATCH * HID;
    int write_hn = ((long long)out_size >= need_hn) ? 1 : 0;
    gru_kernel<<<BATCH * 4, 256>>>(h0, W_hrz, b_hrz, W_hn, b_hn, out, write_hn);
}